// round 1
// baseline (speedup 1.0000x reference)
#include <cuda_runtime.h>
#include <math.h>

// Problem constants
#define B_  8
#define T_  1024
#define C_  1024
#define H_  16
#define DH_ 64
#define M_  (B_*T_)      // 8192 rows
#define N3  (3*C_)       // 3072

// ---------------------------------------------------------------------------
// Scratch (static __device__ arrays: no allocation allowed)
// ---------------------------------------------------------------------------
__device__ float g_xn  [(size_t)M_*C_];   // layernorm output (reused for LN1 and LN2)
__device__ float g_wqkv[(size_t)C_*N3];   // repacked QKV weights [K=1024, N=3072]
__device__ float g_qkv [(size_t)M_*N3];   // fused Q|K|V activations
__device__ float g_attn[(size_t)M_*C_];   // attention output (heads concatenated)
__device__ float g_x1  [(size_t)M_*C_];   // x + attn proj (residual stream)
__device__ float g_h   [(size_t)M_*C_];   // MLP hidden

// ---------------------------------------------------------------------------
// LayerNorm: one block per row (C=1024), 256 threads, float4 per thread
// ---------------------------------------------------------------------------
__global__ void ln_kernel(const float* __restrict__ x, const float* __restrict__ g,
                          const float* __restrict__ b, float* __restrict__ out)
{
    __shared__ float red[16];
    const int row = blockIdx.x;
    const int t   = threadIdx.x;

    float4 v = ((const float4*)(x + (size_t)row * C_))[t];

    // sum
    float s = v.x + v.y + v.z + v.w;
    #pragma unroll
    for (int o = 16; o; o >>= 1) s += __shfl_xor_sync(0xffffffffu, s, o);
    if ((t & 31) == 0) red[t >> 5] = s;
    __syncthreads();
    if (t < 8) {
        float u = red[t];
        #pragma unroll
        for (int o = 4; o; o >>= 1) u += __shfl_xor_sync(0xffu, u, o);
        if (t == 0) red[8] = u;
    }
    __syncthreads();
    const float mean = red[8] * (1.0f / C_);

    // variance
    float dx = v.x - mean, dy = v.y - mean, dz = v.z - mean, dw = v.w - mean;
    float sq = dx*dx + dy*dy + dz*dz + dw*dw;
    #pragma unroll
    for (int o = 16; o; o >>= 1) sq += __shfl_xor_sync(0xffffffffu, sq, o);
    __syncthreads();  // protect red[0..7] reuse
    if ((t & 31) == 0) red[t >> 5] = sq;
    __syncthreads();
    if (t < 8) {
        float u = red[t];
        #pragma unroll
        for (int o = 4; o; o >>= 1) u += __shfl_xor_sync(0xffu, u, o);
        if (t == 0) red[9] = u;
    }
    __syncthreads();
    const float var  = red[9] * (1.0f / C_);
    const float rstd = rsqrtf(var + 1e-5f);

    float4 gg = ((const float4*)g)[t];
    float4 bb = ((const float4*)b)[t];
    float4 o4;
    o4.x = dx * rstd * gg.x + bb.x;
    o4.y = dy * rstd * gg.y + bb.y;
    o4.z = dz * rstd * gg.z + bb.z;
    o4.w = dw * rstd * gg.w + bb.w;
    ((float4*)(out + (size_t)row * C_))[t] = o4;
}

// ---------------------------------------------------------------------------
// Repack Wq/Wk/Wv ([H,C,Dh] each) into one [K=C, N=3C] row-major matrix so that
// the fused QKV GEMM output column n maps to (q|k|v, head, dim).
// ---------------------------------------------------------------------------
__global__ void repack_kernel(const float* __restrict__ Wq, const float* __restrict__ Wk,
                              const float* __restrict__ Wv, float* __restrict__ W)
{
    int idx = blockIdx.x * 256 + threadIdx.x;          // over C_*N3 = 3,145,728
    if (idx >= C_ * N3) return;
    int k  = idx / N3;
    int n  = idx - k * N3;
    int wh = n >> 10;           // 0=Q 1=K 2=V
    int nn = n & 1023;
    int h  = nn >> 6, d = nn & 63;
    const float* src = (wh == 0) ? Wq : (wh == 1) ? Wk : Wv;
    W[idx] = src[(size_t)h * C_ * DH_ + (size_t)k * DH_ + d];
}

// ---------------------------------------------------------------------------
// FP32 tiled GEMM: C[M,N] = A[M,K] @ B[K,N]   (+ epilogues)
//   EPI 0: plain store
//   EPI 1: C = res + acc + bias   (proj / fc2 with residual)
//   EPI 2: C = relu(acc + bias)   (fc1)
// 128x128 block tile, BK=16, 256 threads, 8x8 per thread (split-64 fragments).
// ---------------------------------------------------------------------------
template<int EPI>
__global__ void __launch_bounds__(256, 2) gemm_kernel(
    const float* __restrict__ A, const float* __restrict__ Bm,
    const float* __restrict__ bias, const float* __restrict__ res,
    float* __restrict__ C, int M, int N, int K)
{
    __shared__ float As[16][132];   // A transposed: As[k][m], padded for bank-friendly stores
    __shared__ float Bs[16][128];

    const int tid  = threadIdx.x;
    const int ty   = tid >> 4, tx = tid & 15;
    const int row0 = blockIdx.y * 128, col0 = blockIdx.x * 128;
    const int arow = tid >> 2, acol = (tid & 3) << 2;   // A loads: 128 rows x 16 cols
    const int brow = tid >> 5, bcol = (tid & 31) << 2;  // B loads: 16 rows x 128 cols

    float acc[8][8];
    #pragma unroll
    for (int i = 0; i < 8; i++)
        #pragma unroll
        for (int j = 0; j < 8; j++) acc[i][j] = 0.f;

    for (int k0 = 0; k0 < K; k0 += 16) {
        #pragma unroll
        for (int i = 0; i < 2; i++) {
            float4 a = *(const float4*)(A + (size_t)(row0 + arow + i*64) * K + k0 + acol);
            As[acol+0][arow + i*64] = a.x;
            As[acol+1][arow + i*64] = a.y;
            As[acol+2][arow + i*64] = a.z;
            As[acol+3][arow + i*64] = a.w;
        }
        #pragma unroll
        for (int i = 0; i < 2; i++) {
            *(float4*)&Bs[brow + i*8][bcol] =
                *(const float4*)(Bm + (size_t)(k0 + brow + i*8) * N + col0 + bcol);
        }
        __syncthreads();

        #pragma unroll
        for (int k = 0; k < 16; k++) {
            float ra[8], rb[8];
            *(float4*)(ra)     = *(const float4*)&As[k][ty*4];
            *(float4*)(ra + 4) = *(const float4*)&As[k][64 + ty*4];
            *(float4*)(rb)     = *(const float4*)&Bs[k][tx*4];
            *(float4*)(rb + 4) = *(const float4*)&Bs[k][64 + tx*4];
            #pragma unroll
            for (int i = 0; i < 8; i++)
                #pragma unroll
                for (int j = 0; j < 8; j++)
                    acc[i][j] = fmaf(ra[i], rb[j], acc[i][j]);
        }
        __syncthreads();
    }

    #pragma unroll
    for (int i = 0; i < 8; i++) {
        int r = row0 + ((i < 4) ? (ty*4 + i) : (64 + ty*4 + (i-4)));
        #pragma unroll
        for (int jh = 0; jh < 2; jh++) {
            int c = col0 + ((jh == 0) ? tx*4 : 64 + tx*4);
            float4 v;
            v.x = acc[i][jh*4+0]; v.y = acc[i][jh*4+1];
            v.z = acc[i][jh*4+2]; v.w = acc[i][jh*4+3];
            if (EPI == 1) {
                float4 bb = *(const float4*)(bias + c);
                float4 rr = *(const float4*)(res + (size_t)r * N + c);
                v.x += bb.x + rr.x; v.y += bb.y + rr.y;
                v.z += bb.z + rr.z; v.w += bb.w + rr.w;
            } else if (EPI == 2) {
                float4 bb = *(const float4*)(bias + c);
                v.x = fmaxf(v.x + bb.x, 0.f); v.y = fmaxf(v.y + bb.y, 0.f);
                v.z = fmaxf(v.z + bb.z, 0.f); v.w = fmaxf(v.w + bb.w, 0.f);
            }
            *(float4*)(C + (size_t)r * N + c) = v;
        }
    }
}

// ---------------------------------------------------------------------------
// Flash attention (fp32, causal). One block per (b, h, q-tile of 64).
// 256 threads as 16x16, each owning a 4x4 micro-tile of the 64x64 S / O tiles.
// Online softmax across K/V tiles of 64 (only lower-triangular tiles visited).
// qkv layout: [b*T + t, 3072] with cols [0:1024)=Q, [1024:2048)=K, [2048:3072)=V,
//   each sub-block indexed h*64 + d. Output: [b*T + t, h*64 + d].
// ---------------------------------------------------------------------------
__global__ void __launch_bounds__(256) attn_kernel(const float* __restrict__ qkv,
                                                   float* __restrict__ out)
{
    extern __shared__ float sm[];
    float* Qs = sm;                 // 64 x 65
    float* Ks = Qs + 64*65;         // 64 x 65
    float* Ps = Ks + 64*65;         // 64 x 65
    float* Vs = Ps + 64*65;         // 64 x 64 (float4-friendly)

    const int tid = threadIdx.x;
    const int ty  = tid >> 4, tx = tid & 15;
    const int qt  = blockIdx.x, h = blockIdx.y, b = blockIdx.z;
    const int q0  = qt * 64;
    const float* base = qkv + (size_t)b * T_ * N3 + h * 64;

    // Load Q tile (64 x 64)
    #pragma unroll
    for (int t = 0; t < 4; t++) {
        int idx = tid + t * 256;
        int r = idx >> 4, c = (idx & 15) << 2;
        float4 q4 = *(const float4*)(base + (size_t)(q0 + r) * N3 + c);
        Qs[r*65 + c    ] = q4.x;
        Qs[r*65 + c + 1] = q4.y;
        Qs[r*65 + c + 2] = q4.z;
        Qs[r*65 + c + 3] = q4.w;
    }

    float m[4], l[4], o[4][4];
    #pragma unroll
    for (int i = 0; i < 4; i++) {
        m[i] = -1e30f; l[i] = 0.f;
        #pragma unroll
        for (int d = 0; d < 4; d++) o[i][d] = 0.f;
    }
    const float scale = 0.125f;   // Dh^-0.5

    for (int kt = 0; kt <= qt; kt++) {
        const int k0 = kt * 64;
        __syncthreads();   // prior PV reads done (also covers Q store -> S compute)

        // Load K, V tiles
        #pragma unroll
        for (int t = 0; t < 4; t++) {
            int idx = tid + t * 256;
            int r = idx >> 4, c = (idx & 15) << 2;
            float4 k4 = *(const float4*)(base + 1024 + (size_t)(k0 + r) * N3 + c);
            Ks[r*65 + c    ] = k4.x;
            Ks[r*65 + c + 1] = k4.y;
            Ks[r*65 + c + 2] = k4.z;
            Ks[r*65 + c + 3] = k4.w;
            float4 v4 = *(const float4*)(base + 2048 + (size_t)(k0 + r) * N3 + c);
            *(float4*)&Vs[r*64 + c] = v4;
        }
        __syncthreads();

        // S = Q K^T (4x4 per thread)
        float s[4][4];
        #pragma unroll
        for (int i = 0; i < 4; i++)
            #pragma unroll
            for (int j = 0; j < 4; j++) s[i][j] = 0.f;

        #pragma unroll 4
        for (int k = 0; k < 64; k++) {
            float qr[4], kr[4];
            #pragma unroll
            for (int i = 0; i < 4; i++) qr[i] = Qs[(ty*4 + i)*65 + k];
            #pragma unroll
            for (int j = 0; j < 4; j++) kr[j] = Ks[(tx*4 + j)*65 + k];
            #pragma unroll
            for (int i = 0; i < 4; i++)
                #pragma unroll
                for (int j = 0; j < 4; j++)
                    s[i][j] = fmaf(qr[i], kr[j], s[i][j]);
        }

        const bool diag = (kt == qt);
        #pragma unroll
        for (int i = 0; i < 4; i++) {
            const int qi = q0 + ty*4 + i;
            float rowm = -1e30f;
            #pragma unroll
            for (int j = 0; j < 4; j++) {
                float sv = s[i][j] * scale;
                if (diag && (k0 + tx*4 + j) > qi) sv = -1e30f;
                s[i][j] = sv;
                rowm = fmaxf(rowm, sv);
            }
            #pragma unroll
            for (int off = 8; off; off >>= 1)
                rowm = fmaxf(rowm, __shfl_xor_sync(0xffffffffu, rowm, off));

            const float mn    = fmaxf(m[i], rowm);
            const float alpha = __expf(m[i] - mn);
            m[i] = mn;

            float rs = 0.f;
            #pragma unroll
            for (int j = 0; j < 4; j++) {
                float p = __expf(s[i][j] - mn);
                Ps[(ty*4 + i)*65 + tx*4 + j] = p;
                rs += p;
            }
            #pragma unroll
            for (int off = 8; off; off >>= 1)
                rs += __shfl_xor_sync(0xffffffffu, rs, off);

            l[i] = l[i] * alpha + rs;
            #pragma unroll
            for (int d = 0; d < 4; d++) o[i][d] *= alpha;
        }
        __syncthreads();   // Ps visible

        // O += P @ V
        #pragma unroll 4
        for (int j = 0; j < 64; j++) {
            float4 vv = *(const float4*)&Vs[j*64 + tx*4];
            float pr[4];
            #pragma unroll
            for (int i = 0; i < 4; i++) pr[i] = Ps[(ty*4 + i)*65 + j];
            #pragma unroll
            for (int i = 0; i < 4; i++) {
                o[i][0] = fmaf(pr[i], vv.x, o[i][0]);
                o[i][1] = fmaf(pr[i], vv.y, o[i][1]);
                o[i][2] = fmaf(pr[i], vv.z, o[i][2]);
                o[i][3] = fmaf(pr[i], vv.w, o[i][3]);
            }
        }
    }

    // Write normalized output, heads-concatenated layout [b*T+t, h*64+d]
    #pragma unroll
    for (int i = 0; i < 4; i++) {
        const float inv = 1.0f / l[i];
        float4 v;
        v.x = o[i][0]*inv; v.y = o[i][1]*inv; v.z = o[i][2]*inv; v.w = o[i][3]*inv;
        *(float4*)(out + (size_t)(b*T_ + q0 + ty*4 + i) * C_ + h*64 + tx*4) = v;
    }
}

// ---------------------------------------------------------------------------
// Launch
// ---------------------------------------------------------------------------
static const int ATTN_SMEM = (3*64*65 + 64*64) * sizeof(float);  // 66304 B

extern "C" void kernel_launch(void* const* d_in, const int* in_sizes, int n_in,
                              void* d_out, int out_size)
{
    const float* x     = (const float*)d_in[0];
    const float* Wq    = (const float*)d_in[1];
    const float* Wk    = (const float*)d_in[2];
    const float* Wv    = (const float*)d_in[3];
    const float* Wproj = (const float*)d_in[4];
    const float* bproj = (const float*)d_in[5];
    const float* W1    = (const float*)d_in[6];
    const float* b1    = (const float*)d_in[7];
    const float* W2    = (const float*)d_in[8];
    const float* b2    = (const float*)d_in[9];
    const float* g1    = (const float*)d_in[10];
    const float* be1   = (const float*)d_in[11];
    const float* g2    = (const float*)d_in[12];
    const float* be2   = (const float*)d_in[13];
    float* out = (float*)d_out;

    float *xn, *wqkv, *qkv, *attn, *x1, *hbuf;
    cudaGetSymbolAddress((void**)&xn,   g_xn);
    cudaGetSymbolAddress((void**)&wqkv, g_wqkv);
    cudaGetSymbolAddress((void**)&qkv,  g_qkv);
    cudaGetSymbolAddress((void**)&attn, g_attn);
    cudaGetSymbolAddress((void**)&x1,   g_x1);
    cudaGetSymbolAddress((void**)&hbuf, g_h);

    // Raise dynamic smem cap for attention (idempotent; errors ignored — the
    // attribute persists from the pre-capture correctness call).
    cudaFuncSetAttribute(attn_kernel, cudaFuncAttributeMaxDynamicSharedMemorySize, ATTN_SMEM);

    // 1. LN1
    ln_kernel<<<M_, 256>>>(x, g1, be1, xn);
    // 2. repack QKV weights -> [1024, 3072]
    repack_kernel<<<(C_*N3 + 255)/256, 256>>>(Wq, Wk, Wv, wqkv);
    // 3. fused QKV GEMM: [8192,1024] @ [1024,3072]
    gemm_kernel<0><<<dim3(N3/128, M_/128), 256>>>(xn, wqkv, nullptr, nullptr, qkv, M_, N3, C_);
    // 4. causal flash attention
    attn_kernel<<<dim3(T_/64, H_, B_), 256, ATTN_SMEM>>>(qkv, attn);
    // 5. output projection + bias + residual: x1 = x + attn @ Wproj + bproj
    gemm_kernel<1><<<dim3(C_/128, M_/128), 256>>>(attn, Wproj, bproj, x, x1, M_, C_, C_);
    // 6. LN2
    ln_kernel<<<M_, 256>>>(x1, g2, be2, xn);
    // 7. fc1 + ReLU
    gemm_kernel<2><<<dim3(C_/128, M_/128), 256>>>(xn, W1, b1, nullptr, hbuf, M_, C_, C_);
    // 8. fc2 + bias + residual -> out
    gemm_kernel<1><<<dim3(C_/128, M_/128), 256>>>(hbuf, W2, b2, x1, out, M_, C_, C_);
}